// round 5
// baseline (speedup 1.0000x reference)
#include <cuda_runtime.h>
#include <math.h>

#define HH   112
#define WW   512
#define CI   64
#define CLm  32
#define NPIX (HH*WW)      // 57344
#define M1   (HH*16)      // 1792
#define KD   (HH*CLm)     // 3584
#define SPLITK 4
#define KSPL (KD/SPLITK)  // 896
#define EG   4            // experts per stage-3 block

// ---------------- scratch (static device globals; no allocation) ----------------
__device__ float  g_hf[KD*WW];           // [3584,512]  stage-1 output
__device__ float  g_x1p[SPLITK*M1*WW];   // split-K partials of d3 GEMM
__device__ float  g_xt[NPIX*CI];         // [pix,64]    transposed input
__device__ int    g_inds1[NPIX];
__device__ int    g_inds12[NPIX];        // UNCLIPPED inds12
__device__ double g_acc[16];             // [0]=ce1, [1..6]=branch nll, [8..13]=branch mask

__device__ __forceinline__ float leakyf(float v){ return v > 0.f ? v : 0.01f*v; }

__device__ __forceinline__ unsigned long long pack2(float lo, float hi){
    unsigned long long r;
    asm("mov.b64 %0, {%1, %2};" : "=l"(r) : "f"(lo), "f"(hi));
    return r;
}
__device__ __forceinline__ unsigned long long fma2(
    unsigned long long a, unsigned long long b, unsigned long long c){
    unsigned long long d;
    asm("fma.rn.f32x2 %0, %1, %2, %3;" : "=l"(d) : "l"(a), "l"(b), "l"(c));
    return d;
}

// ---------------- K0: zero accumulators ----------------
__global__ void k_zero()
{
    if (threadIdx.x < 16) g_acc[threadIdx.x] = 0.0;
}

// ---------------- K1: transpose x_in [ci,H,W] -> g_xt [pix,ci] ----------------
__global__ void k_transpose(const float* __restrict__ x_in)
{
    __shared__ float tile[32][33];
    int p0 = blockIdx.x * 32;
    int i0 = blockIdx.y * 32;
    int tx = threadIdx.x, ty = threadIdx.y;
#pragma unroll
    for (int r = ty; r < 32; r += 8)
        tile[r][tx] = x_in[(size_t)(i0 + r) * NPIX + p0 + tx];
    __syncthreads();
#pragma unroll
    for (int r = ty; r < 32; r += 8)
        g_xt[(size_t)(p0 + r) * CI + i0 + tx] = tile[tx][r];
}

// ---------------- K2: stage-1 grouped convs -> g_hf ----------------
__global__ void k_stage1(const float* __restrict__ x_in,
                         const float* __restrict__ g1w, const float* __restrict__ g1b,
                         const float* __restrict__ g2w, const float* __restrict__ g2b)
{
    __shared__ float w1T[CI*CLm];   // [i][o]
    __shared__ float w2T[CLm*CLm];  // [i][o]
    __shared__ float b1s[CLm], b2s[CLm];
    int h = blockIdx.x, tid = threadIdx.x;
    for (int idx = tid; idx < CI*CLm; idx += 128) {
        int o = idx >> 6, i = idx & 63;
        w1T[i*CLm + o] = g1w[(size_t)h*CI*CLm + idx];
    }
    for (int idx = tid; idx < CLm*CLm; idx += 128) {
        int o = idx >> 5, i = idx & 31;
        w2T[i*CLm + o] = g2w[(size_t)h*CLm*CLm + idx];
    }
    if (tid < CLm) { b1s[tid] = g1b[h*CLm + tid]; b2s[tid] = g2b[h*CLm + tid]; }
    __syncthreads();

    for (int w = tid; w < WW; w += 128) {
        float h1[CLm];
#pragma unroll
        for (int o = 0; o < CLm; o++) h1[o] = b1s[o];
#pragma unroll 4
        for (int i = 0; i < CI; i++) {
            float xi = x_in[(size_t)i*NPIX + h*WW + w];
#pragma unroll
            for (int o = 0; o < CLm; o++) h1[o] = fmaf(xi, w1T[i*CLm + o], h1[o]);
        }
#pragma unroll
        for (int o = 0; o < CLm; o++) h1[o] = leakyf(h1[o]);
        float h2[CLm];
#pragma unroll
        for (int o = 0; o < CLm; o++) h2[o] = b2s[o];
#pragma unroll 4
        for (int i = 0; i < CLm; i++) {
            float v = h1[i];
#pragma unroll
            for (int o = 0; o < CLm; o++) h2[o] = fmaf(v, w2T[i*CLm + o], h2[o]);
        }
#pragma unroll
        for (int o = 0; o < CLm; o++)
            g_hf[(size_t)(h*CLm + o)*WW + w] = leakyf(h2[o]);
    }
}

// ---------------- K3: d3 GEMM split-K, FFMA2 inner (BM64,BN64,BK16,64 thr) -----
__global__ void __launch_bounds__(64)
k_gemm(const float* __restrict__ A)
{
    __shared__ float As[16][68];
    __shared__ float Bs[16][68];
    int t = threadIdx.x;           // 0..63
    int tx = t & 7, ty = t >> 3;   // tx -> n (pairs), ty -> m
    int bm = blockIdx.x * 64, bn = blockIdx.y * 64;
    int kbase = blockIdx.z * KSPL;
    unsigned long long acc2[8][4];
#pragma unroll
    for (int i = 0; i < 8; i++)
#pragma unroll
        for (int j = 0; j < 4; j++) acc2[i][j] = 0ull;

    for (int k0 = kbase; k0 < kbase + KSPL; k0 += 16) {
#pragma unroll
        for (int r = 0; r < 4; r++) {
            int c = t + 64*r;
            int row = c >> 2, kc = (c & 3) * 4;
            float4 a4 = *(const float4*)(A + (size_t)(bm+row)*KD + k0 + kc);
            As[kc+0][row] = a4.x; As[kc+1][row] = a4.y;
            As[kc+2][row] = a4.z; As[kc+3][row] = a4.w;
        }
#pragma unroll
        for (int r = 0; r < 4; r++) {
            int c = t + 64*r;
            int kk = c >> 4, nn = (c & 15) * 4;
            *(float4*)&Bs[kk][nn] =
                *(const float4*)(g_hf + (size_t)(k0+kk)*WW + bn + nn);
        }
        __syncthreads();
#pragma unroll
        for (int k = 0; k < 16; k++) {
            float4 a0 = *(const float4*)&As[k][ty*8];
            float4 a1 = *(const float4*)&As[k][ty*8+4];
            float av[8] = {a0.x,a0.y,a0.z,a0.w,a1.x,a1.y,a1.z,a1.w};
            unsigned long long a2[8];
#pragma unroll
            for (int i = 0; i < 8; i++) a2[i] = pack2(av[i], av[i]);
            unsigned long long b2[4];
#pragma unroll
            for (int j = 0; j < 4; j++)
                b2[j] = *(const unsigned long long*)&Bs[k][tx*8 + 2*j];
#pragma unroll
            for (int i = 0; i < 8; i++)
#pragma unroll
                for (int j = 0; j < 4; j++)
                    acc2[i][j] = fma2(a2[i], b2[j], acc2[i][j]);
        }
        __syncthreads();
    }
    float* outp = g_x1p + (size_t)blockIdx.z * M1 * WW;
    union U { unsigned long long u; float2 f; };
#pragma unroll
    for (int i = 0; i < 8; i++) {
        int row = bm + ty*8 + i;
        U u0, u1, u2, u3;
        u0.u = acc2[i][0]; u1.u = acc2[i][1]; u2.u = acc2[i][2]; u3.u = acc2[i][3];
        *(float4*)(outp + (size_t)row*WW + bn + tx*8)     =
            make_float4(u0.f.x, u0.f.y, u1.f.x, u1.f.y);
        *(float4*)(outp + (size_t)row*WW + bn + tx*8 + 4) =
            make_float4(u2.f.x, u2.f.y, u3.f.x, u3.f.y);
    }
}

// ---------------- K4: sum partials + bias, argmax -> inds1, CE loss[0] ----------
__global__ void k_s1head(const int* __restrict__ inds_gt, const float* __restrict__ bias)
{
    int pix = blockIdx.x * 256 + threadIdx.x;
    int h = pix >> 9, w = pix & 511;
    float v[16];
    float mx = -1e30f; int mi = 0;
#pragma unroll
    for (int c = 0; c < 16; c++) {
        float s = bias[h*16 + c];
#pragma unroll
        for (int z = 0; z < SPLITK; z++)
            s += g_x1p[(size_t)z*M1*WW + (size_t)(h*16 + c)*WW + w];
        v[c] = s;
        if (s > mx) { mx = s; mi = c; }
    }
    g_inds1[pix] = mi;
    int g = min(max(inds_gt[pix], 0), 4095);
    int t = g >> 8;
    float se = 0.f;
#pragma unroll
    for (int c = 0; c < 16; c++) se += expf(v[c] - mx);
    float nll = mx + logf(se) - v[t];

    __shared__ float red[256];
    red[threadIdx.x] = nll;
    __syncthreads();
    for (int o = 128; o; o >>= 1) {
        if (threadIdx.x < o) red[threadIdx.x] += red[threadIdx.x + o];
        __syncthreads();
    }
    if (threadIdx.x == 0) atomicAdd(&g_acc[0], (double)red[0]);
}

// ======== grouped gather machinery (natural [in][out] weight layout) ==========

// evaluate 4 pixels through the 64->32->32->32 MLP; lane = output channel.
__device__ __forceinline__ void eval4(
    const float* __restrict__ w1s, const float* __restrict__ w2s,
    const float* __restrict__ w3s,
    const float* __restrict__ b1s, const float* __restrict__ b2s,
    const float* __restrict__ b3s,
    const int* pix, float* xbw, float* ybw, int lane, float y3[4])
{
    {
        int jj = lane & 3, q = lane >> 2;
        const float* xp = g_xt + (size_t)pix[jj]*64;
#pragma unroll
        for (int r = 0; r < 8; r++)
            xbw[jj*68 + q + 8*r] = xp[q + 8*r];
    }
    __syncwarp();
    float a0 = b1s[lane], a1 = a0, a2 = a0, a3 = a0;
#pragma unroll
    for (int i4 = 0; i4 < 16; i4++) {
        float4 x0 = *(const float4*)(xbw + 0*68 + i4*4);
        float4 x1 = *(const float4*)(xbw + 1*68 + i4*4);
        float4 x2 = *(const float4*)(xbw + 2*68 + i4*4);
        float4 x3 = *(const float4*)(xbw + 3*68 + i4*4);
        const float* wp = w1s + i4*128 + lane;
        float w0 = wp[0], w1 = wp[32], w2 = wp[64], w3 = wp[96];
        a0 = fmaf(x0.x,w0,a0); a0 = fmaf(x0.y,w1,a0); a0 = fmaf(x0.z,w2,a0); a0 = fmaf(x0.w,w3,a0);
        a1 = fmaf(x1.x,w0,a1); a1 = fmaf(x1.y,w1,a1); a1 = fmaf(x1.z,w2,a1); a1 = fmaf(x1.w,w3,a1);
        a2 = fmaf(x2.x,w0,a2); a2 = fmaf(x2.y,w1,a2); a2 = fmaf(x2.z,w2,a2); a2 = fmaf(x2.w,w3,a2);
        a3 = fmaf(x3.x,w0,a3); a3 = fmaf(x3.y,w1,a3); a3 = fmaf(x3.z,w2,a3); a3 = fmaf(x3.w,w3,a3);
    }
    a0 = leakyf(a0); a1 = leakyf(a1); a2 = leakyf(a2); a3 = leakyf(a3);
    ybw[0*36+lane] = a0; ybw[1*36+lane] = a1; ybw[2*36+lane] = a2; ybw[3*36+lane] = a3;
    __syncwarp();
    float c0 = b2s[lane], c1 = c0, c2 = c0, c3 = c0;
#pragma unroll
    for (int i4 = 0; i4 < 8; i4++) {
        float4 x0 = *(const float4*)(ybw + 0*36 + i4*4);
        float4 x1 = *(const float4*)(ybw + 1*36 + i4*4);
        float4 x2 = *(const float4*)(ybw + 2*36 + i4*4);
        float4 x3 = *(const float4*)(ybw + 3*36 + i4*4);
        const float* wp = w2s + i4*128 + lane;
        float w0 = wp[0], w1 = wp[32], w2 = wp[64], w3 = wp[96];
        c0 = fmaf(x0.x,w0,c0); c0 = fmaf(x0.y,w1,c0); c0 = fmaf(x0.z,w2,c0); c0 = fmaf(x0.w,w3,c0);
        c1 = fmaf(x1.x,w0,c1); c1 = fmaf(x1.y,w1,c1); c1 = fmaf(x1.z,w2,c1); c1 = fmaf(x1.w,w3,c1);
        c2 = fmaf(x2.x,w0,c2); c2 = fmaf(x2.y,w1,c2); c2 = fmaf(x2.z,w2,c2); c2 = fmaf(x2.w,w3,c2);
        c3 = fmaf(x3.x,w0,c3); c3 = fmaf(x3.y,w1,c3); c3 = fmaf(x3.z,w2,c3); c3 = fmaf(x3.w,w3,c3);
    }
    c0 = leakyf(c0); c1 = leakyf(c1); c2 = leakyf(c2); c3 = leakyf(c3);
    __syncwarp();
    ybw[0*36+lane] = c0; ybw[1*36+lane] = c1; ybw[2*36+lane] = c2; ybw[3*36+lane] = c3;
    __syncwarp();
    float d0 = b3s[lane], d1 = d0, d2 = d0, d3 = d0;
#pragma unroll
    for (int i4 = 0; i4 < 8; i4++) {
        float4 x0 = *(const float4*)(ybw + 0*36 + i4*4);
        float4 x1 = *(const float4*)(ybw + 1*36 + i4*4);
        float4 x2 = *(const float4*)(ybw + 2*36 + i4*4);
        float4 x3 = *(const float4*)(ybw + 3*36 + i4*4);
        const float* wp = w3s + i4*128 + lane;
        float w0 = wp[0], w1 = wp[32], w2 = wp[64], w3 = wp[96];
        d0 = fmaf(x0.x,w0,d0); d0 = fmaf(x0.y,w1,d0); d0 = fmaf(x0.z,w2,d0); d0 = fmaf(x0.w,w3,d0);
        d1 = fmaf(x1.x,w0,d1); d1 = fmaf(x1.y,w1,d1); d1 = fmaf(x1.z,w2,d1); d1 = fmaf(x1.w,w3,d1);
        d2 = fmaf(x2.x,w0,d2); d2 = fmaf(x2.y,w1,d2); d2 = fmaf(x2.z,w2,d2); d2 = fmaf(x2.w,w3,d2);
        d3 = fmaf(x3.x,w0,d3); d3 = fmaf(x3.y,w1,d3); d3 = fmaf(x3.z,w2,d3); d3 = fmaf(x3.w,w3,d3);
    }
    y3[0] = d0; y3[1] = d1; y3[2] = d2; y3[3] = d3;
    __syncwarp();
}

// K5: stage-2 fused forward + 3 loss branches; grid (16, 112) — static smem
struct SmemW {
    float w1s[2048], w2s[1024], w3s[1024];
    float b1s[32], b2s[32], b3s[32];
};

__device__ __forceinline__ void load_weights(
    const float* __restrict__ w1, const float* __restrict__ w2,
    const float* __restrict__ w3,
    const float* __restrict__ b1, const float* __restrict__ b2,
    const float* __restrict__ b3, SmemW* sw, int tid)
{
#pragma unroll
    for (int r = 0; r < 2; r++)
        ((float4*)sw->w1s)[tid + 256*r] = ((const float4*)w1)[tid + 256*r];
    ((float4*)sw->w2s)[tid] = ((const float4*)w2)[tid];
    ((float4*)sw->w3s)[tid] = ((const float4*)w3)[tid];
    if (tid < 32) { sw->b1s[tid] = b1[tid]; sw->b2s[tid] = b2[tid]; sw->b3s[tid] = b3[tid]; }
}

__global__ void __launch_bounds__(256)
k_s2all(const int* __restrict__ inds_gt,
        const float* __restrict__ w1g, const float* __restrict__ b1g,
        const float* __restrict__ w2g, const float* __restrict__ b2g,
        const float* __restrict__ w3g, const float* __restrict__ b3g)
{
    __shared__ SmemW sw;
    __shared__ float xb[8][272];
    __shared__ float yb[8][144];
    __shared__ unsigned entries[2048];
    __shared__ int cnt, mcnt[3];
    __shared__ float nacc[3];

    int e = blockIdx.x, h = blockIdx.y;
    int tid = threadIdx.x;
    int row = h << 9;
    if (tid == 0) cnt = 0;
    if (tid < 3) { mcnt[tid] = 0; nacc[tid] = 0.f; }
    __syncthreads();

#pragma unroll
    for (int r = 0; r < 2; r++) {
        int p = tid + 256*r;
        if (g_inds1[row + p] == e)
            entries[atomicAdd(&cnt, 1)] = (unsigned)(p | (3u << 9));
        int g = min(max(inds_gt[row + p], 0), 4095);
#pragma unroll
        for (int i = -1; i <= 1; i++) {
            int i1 = min(max((g >> 8) + i, 0), 15);
            if (i1 == e) {
                int tr = (g >> 4) - i1*16 + 8;
                int mk = (tr >= 0 && tr < 32) ? 1 : 0;
                int tt = min(max(tr, 0), 31);
                int b = i + 1;
                entries[atomicAdd(&cnt, 1)] =
                    (unsigned)(p | (b << 9) | (tt << 11) | (mk << 16));
                if (mk) atomicAdd(&mcnt[b], 1);
            }
        }
    }
    __syncthreads();
    int n = cnt;
    if (n == 0) return;

    size_t eg = (size_t)(e + 16*h);
    load_weights(w1g + eg*2048, w2g + eg*1024, w3g + eg*1024,
                 b1g + eg*32,   b2g + eg*32,   b3g + eg*32, &sw, tid);
    __syncthreads();

    int w = tid >> 5, lane = tid & 31;
    for (int gidx = w; gidx*4 < n; gidx += 8) {
        int base = gidx*4;
        int m = min(4, n - base);
        unsigned ent[4]; int pix[4];
#pragma unroll
        for (int j = 0; j < 4; j++) {
            ent[j] = entries[base + min(j, m-1)];
            pix[j] = row + (int)(ent[j] & 511u);
        }
        float y3[4];
        eval4(sw.w1s, sw.w2s, sw.w3s, sw.b1s, sw.b2s, sw.b3s,
              pix, xb[w], yb[w], lane, y3);
#pragma unroll
        for (int j = 0; j < 4; j++) {
            if (j >= m) break;
            int br = (ent[j] >> 9) & 3;
            float y = y3[j];
            if (br == 3) {
                float bvv = y; int bi = lane;
#pragma unroll
                for (int off = 16; off; off >>= 1) {
                    float ov = __shfl_xor_sync(0xffffffffu, bvv, off);
                    int   oi = __shfl_xor_sync(0xffffffffu, bi, off);
                    if (ov > bvv || (ov == bvv && oi < bi)) { bvv = ov; bi = oi; }
                }
                if (lane == 0) g_inds12[pix[j]] = e*16 + bi - 8;
            } else {
                int tt = (ent[j] >> 11) & 31;
                float mv = y;
#pragma unroll
                for (int off = 16; off; off >>= 1)
                    mv = fmaxf(mv, __shfl_xor_sync(0xffffffffu, mv, off));
                float s = expf(y - mv);
#pragma unroll
                for (int off = 16; off; off >>= 1)
                    s += __shfl_xor_sync(0xffffffffu, s, off);
                float vt = __shfl_sync(0xffffffffu, y, tt);
                if (lane == 0) atomicAdd(&nacc[br], mv + logf(s) - vt);
            }
        }
    }
    __syncthreads();
    if (tid < 3) {
        atomicAdd(&g_acc[1 + tid], (double)nacc[tid]);
        atomicAdd(&g_acc[8 + tid], (double)mcnt[tid]);
    }
}

// K6: stage-3, EG=4 experts per block; grid (64, 112); dynamic smem
// layout: W1[4][2048] | W2[4][1024] | W3[4][1024] | B1/B2/B3[4][32] |
//         XB[8][272] | YB[8][144] | ENT[2048] (unsigned) | control ints
#define S3_SMEM_FLOATS (EG*2048 + EG*1024 + EG*1024 + 3*EG*32 + 8*272 + 8*144 + 2048 + 32)
#define S3_SMEM_BYTES  (S3_SMEM_FLOATS * 4)

__global__ void __launch_bounds__(256)
k_s3all(const int* __restrict__ inds_gt,
        const float* __restrict__ w1g, const float* __restrict__ b1g,
        const float* __restrict__ w2g, const float* __restrict__ b2g,
        const float* __restrict__ w3g, const float* __restrict__ b3g,
        float* __restrict__ outF)
{
    extern __shared__ float smem[];
    float* W1 = smem;                 // [4][2048]
    float* W2 = W1 + EG*2048;         // [4][1024]
    float* W3 = W2 + EG*1024;         // [4][1024]
    float* B1 = W3 + EG*1024;         // [4][32]
    float* B2 = B1 + EG*32;
    float* B3 = B2 + EG*32;
    float* XB = B3 + EG*32;           // [8][272]
    float* YB = XB + 8*272;           // [8][144]
    unsigned* ENT = (unsigned*)(YB + 8*144);   // [2048]
    int* CTL = (int*)(ENT + 2048);
    int* cnt4 = CTL;                  // [4] counts
    int* seg4 = CTL + 4;              // [4] segment starts
    int* cur4 = CTL + 8;              // [4] cursors
    int* mcnt = CTL + 12;             // [3]
    float* nacc = (float*)(CTL + 16); // [3]

    int e0 = blockIdx.x * EG, h = blockIdx.y;
    int tid = threadIdx.x;
    int row = h << 9;
    if (tid < 4) { cnt4[tid] = 0; }
    if (tid < 3) { mcnt[tid] = 0; nacc[tid] = 0.f; }
    __syncthreads();

    // pass 1: count tasks per local expert
#pragma unroll
    for (int r = 0; r < 2; r++) {
        int p = tid + 256*r;
        int raw = g_inds12[row + p];
        int le = min(max(raw, 0), 255) - e0;
        if (le >= 0 && le < EG) atomicAdd(&cnt4[le], 1);
        int g = min(max(inds_gt[row + p], 0), 4095);
#pragma unroll
        for (int i = -1; i <= 1; i++) {
            int i12 = min(max((g >> 4) + i, 0), 255);
            int l2 = i12 - e0;
            if (l2 >= 0 && l2 < EG) atomicAdd(&cnt4[l2], 1);
        }
    }
    __syncthreads();
    if (tid == 0) {
        int acc = 0;
#pragma unroll
        for (int q = 0; q < EG; q++) { seg4[q] = acc; cur4[q] = acc; acc += cnt4[q]; }
    }
    __syncthreads();
    int cn[EG];
#pragma unroll
    for (int q = 0; q < EG; q++) cn[q] = cnt4[q];
    int ntot = cn[0] + cn[1] + cn[2] + cn[3];
    if (ntot == 0) return;

    // weight load (only for non-empty experts)
#pragma unroll
    for (int q = 0; q < EG; q++) {
        if (cn[q] == 0) continue;
        size_t eg = (size_t)(e0 + q + 256*h);
        const float4* s1 = (const float4*)(w1g + eg*2048);
        const float4* s2 = (const float4*)(w2g + eg*1024);
        const float4* s3 = (const float4*)(w3g + eg*1024);
        float4* d1 = (float4*)(W1 + q*2048);
        float4* d2 = (float4*)(W2 + q*1024);
        float4* d3 = (float4*)(W3 + q*1024);
        d1[tid]       = s1[tid];
        d1[tid + 256] = s1[tid + 256];
        d2[tid]       = s2[tid];
        d3[tid]       = s3[tid];
        if (tid < 32) {
            B1[q*32 + tid] = b1g[eg*32 + tid];
            B2[q*32 + tid] = b2g[eg*32 + tid];
            B3[q*32 + tid] = b3g[eg*32 + tid];
        }
    }

    // pass 2: place tasks into segments
#pragma unroll
    for (int r = 0; r < 2; r++) {
        int p = tid + 256*r;
        int raw = g_inds12[row + p];
        int le = min(max(raw, 0), 255) - e0;
        if (le >= 0 && le < EG)
            ENT[atomicAdd(&cur4[le], 1)] = (unsigned)(p | (3u << 9));
        int g = min(max(inds_gt[row + p], 0), 4095);
#pragma unroll
        for (int i = -1; i <= 1; i++) {
            int i12 = min(max((g >> 4) + i, 0), 255);
            int l2 = i12 - e0;
            if (l2 >= 0 && l2 < EG) {
                int tr = g - i12*16 + 8;
                int mk = (tr >= 0 && tr < 32) ? 1 : 0;
                int tt = min(max(tr, 0), 31);
                int b = i + 1;
                ENT[atomicAdd(&cur4[l2], 1)] =
                    (unsigned)(p | (b << 9) | (tt << 11) | (mk << 16));
                if (mk) atomicAdd(&mcnt[b], 1);
            }
        }
    }
    __syncthreads();

    // chunked work list: chunks of 4 same-expert tasks
    int nch[EG], cst[EG], tot = 0;
#pragma unroll
    for (int q = 0; q < EG; q++) { nch[q] = (cn[q] + 3) >> 2; cst[q] = tot; tot += nch[q]; }

    int w = tid >> 5, lane = tid & 31;
    float* xbw = XB + w*272;
    float* ybw = YB + w*144;
    for (int c = w; c < tot; c += 8) {
        int le = EG - 1;
#pragma unroll
        for (int q = EG - 1; q > 0; q--) if (c < cst[q]) le = q - 1;
        int idx = c - cst[le];
        int base = seg4[le] + idx*4;
        int m = min(4, cn[le] - idx*4);
        unsigned ent[4]; int pix[4];
#pragma unroll
        for (int j = 0; j < 4; j++) {
            ent[j] = ENT[base + min(j, m-1)];
            pix[j] = row + (int)(ent[j] & 511u);
        }
        float y3[4];
        eval4(W1 + le*2048, W2 + le*1024, W3 + le*1024,
              B1 + le*32,   B2 + le*32,   B3 + le*32,
              pix, xbw, ybw, lane, y3);
#pragma unroll
        for (int j = 0; j < 4; j++) {
            if (j >= m) break;
            int br = (ent[j] >> 9) & 3;
            float y = y3[j];
            if (br == 3) {
                float bvv = y; int bi = lane;
#pragma unroll
                for (int off = 16; off; off >>= 1) {
                    float ov = __shfl_xor_sync(0xffffffffu, bvv, off);
                    int   oi = __shfl_xor_sync(0xffffffffu, bi, off);
                    if (ov > bvv || (ov == bvv && oi < bi)) { bvv = ov; bi = oi; }
                }
                if (lane == 0) {
                    int raw = g_inds12[pix[j]];
                    outF[pix[j]] = (float)min(max(raw*16 + bi - 8, 0), 4095);
                }
            } else {
                int tt = (ent[j] >> 11) & 31;
                float mv = y;
#pragma unroll
                for (int off = 16; off; off >>= 1)
                    mv = fmaxf(mv, __shfl_xor_sync(0xffffffffu, mv, off));
                float s = expf(y - mv);
#pragma unroll
                for (int off = 16; off; off >>= 1)
                    s += __shfl_xor_sync(0xffffffffu, s, off);
                float vt = __shfl_sync(0xffffffffu, y, tt);
                if (lane == 0) atomicAdd(&nacc[br], mv + logf(s) - vt);
            }
        }
    }
    __syncthreads();
    if (tid < 3) {
        atomicAdd(&g_acc[4 + tid], (double)nacc[tid]);
        atomicAdd(&g_acc[11 + tid], (double)mcnt[tid]);
    }
}

// ---------------- K8: finalize losses ----------------
__global__ void k_final(float* __restrict__ outF, int base)
{
    if (threadIdx.x == 0) {
        double N = (double)NPIX;
        outF[base] = (float)(g_acc[0] / N);
#pragma unroll
        for (int b = 0; b < 6; b++)
            outF[base + 1 + b] = (float)((g_acc[1 + b] / N) * (g_acc[8 + b] / N));
    }
}

// ---------------- launcher ----------------
extern "C" void kernel_launch(void* const* d_in, const int* in_sizes, int n_in,
                              void* d_out, int out_size)
{
    const float* x_in  = (const float*)d_in[0];
    const float* g1_w  = (const float*)d_in[1];
    const float* g1_b  = (const float*)d_in[2];
    const float* g2_w  = (const float*)d_in[3];
    const float* g2_b  = (const float*)d_in[4];
    const float* d3_w  = (const float*)d_in[5];
    const float* d3_b  = (const float*)d_in[6];
    const float* s2_w1 = (const float*)d_in[7];
    const float* s2_b1 = (const float*)d_in[8];
    const float* s2_w2 = (const float*)d_in[9];
    const float* s2_b2 = (const float*)d_in[10];
    const float* s2_w3 = (const float*)d_in[11];
    const float* s2_b3 = (const float*)d_in[12];
    const float* s3_w1 = (const float*)d_in[13];
    const float* s3_b1 = (const float*)d_in[14];
    const float* s3_w2 = (const float*)d_in[15];
    const float* s3_b2 = (const float*)d_in[16];
    const float* s3_w3 = (const float*)d_in[17];
    const float* s3_b3 = (const float*)d_in[18];
    const int*   igt   = (const int*)d_in[19];
    float* outF = (float*)d_out;

    static int s3_attr_set = 0;
    if (!s3_attr_set) {
        cudaFuncSetAttribute(k_s3all, cudaFuncAttributeMaxDynamicSharedMemorySize,
                             S3_SMEM_BYTES);
        s3_attr_set = 1;
    }

    k_zero<<<1, 32>>>();
    k_transpose<<<dim3(NPIX/32, CI/32), dim3(32, 8)>>>(x_in);
    k_stage1<<<HH, 128>>>(x_in, g1_w, g1_b, g2_w, g2_b);
    k_gemm<<<dim3(M1/64, WW/64, SPLITK), 64>>>(d3_w);
    k_s1head<<<NPIX/256, 256>>>(igt, d3_b);
    k_s2all<<<dim3(16, HH), 256>>>(igt, s2_w1, s2_b1, s2_w2, s2_b2, s2_w3, s2_b3);
    k_s3all<<<dim3(256/EG, HH), 256, S3_SMEM_BYTES>>>(igt,
        s3_w1, s3_b1, s3_w2, s3_b2, s3_w3, s3_b3, outF);
    k_final<<<1, 32>>>(outF, out_size - 7);
}

// round 10
// speedup vs baseline: 1.2618x; 1.2618x over previous
#include <cuda_runtime.h>
#include <math.h>

#define HH   112
#define WW   512
#define CI   64
#define CLm  32
#define NPIX (HH*WW)      // 57344
#define M1   (HH*16)      // 1792
#define KD   (HH*CLm)     // 3584
#define SPLITK 4
#define KSPL (KD/SPLITK)  // 896

// ---------------- scratch (static device globals; no allocation) ----------------
__device__ float  g_hf[KD*WW];           // [3584,512]  stage-1 output
__device__ float  g_x1p[SPLITK*M1*WW];   // split-K partials of d3 GEMM
__device__ float  g_xt[NPIX*CI];         // [pix,64]    transposed input
__device__ int    g_inds1[NPIX];
__device__ int    g_inds12[NPIX];        // UNCLIPPED inds12
__device__ double g_acc[16];             // [0]=ce1, [1..6]=branch nll, [8..13]=branch mask
__device__ unsigned g_ent2[HH*2048];     // stage-2 worklists per row
__device__ int      g_off2[HH*17];
__device__ unsigned g_ent3[HH*2048];     // stage-3 worklists per row
__device__ int      g_off3[HH*257];

__device__ __forceinline__ float leakyf(float v){ return v > 0.f ? v : 0.01f*v; }

__device__ __forceinline__ unsigned long long pack2(float lo, float hi){
    unsigned long long r;
    asm("mov.b64 %0, {%1, %2};" : "=l"(r) : "f"(lo), "f"(hi));
    return r;
}
__device__ __forceinline__ unsigned long long fma2(
    unsigned long long a, unsigned long long b, unsigned long long c){
    unsigned long long d;
    asm("fma.rn.f32x2 %0, %1, %2, %3;" : "=l"(d) : "l"(a), "l"(b), "l"(c));
    return d;
}

// ---------------- K0: zero accumulators ----------------
__global__ void k_zero()
{
    if (threadIdx.x < 16) g_acc[threadIdx.x] = 0.0;
}

// ---------------- K1: transpose x_in [ci,H,W] -> g_xt [pix,ci] ----------------
__global__ void k_transpose(const float* __restrict__ x_in)
{
    __shared__ float tile[32][33];
    int p0 = blockIdx.x * 32;
    int i0 = blockIdx.y * 32;
    int tx = threadIdx.x, ty = threadIdx.y;
#pragma unroll
    for (int r = ty; r < 32; r += 8)
        tile[r][tx] = x_in[(size_t)(i0 + r) * NPIX + p0 + tx];
    __syncthreads();
#pragma unroll
    for (int r = ty; r < 32; r += 8)
        g_xt[(size_t)(p0 + r) * CI + i0 + tx] = tile[tx][r];
}

// ---------------- K2: stage-1 grouped convs -> g_hf ----------------
__global__ void k_stage1(const float* __restrict__ x_in,
                         const float* __restrict__ g1w, const float* __restrict__ g1b,
                         const float* __restrict__ g2w, const float* __restrict__ g2b)
{
    __shared__ float w1T[CI*CLm];   // [i][o]
    __shared__ float w2T[CLm*CLm];  // [i][o]
    __shared__ float b1s[CLm], b2s[CLm];
    int h = blockIdx.x, tid = threadIdx.x;
    for (int idx = tid; idx < CI*CLm; idx += 128) {
        int o = idx >> 6, i = idx & 63;
        w1T[i*CLm + o] = g1w[(size_t)h*CI*CLm + idx];
    }
    for (int idx = tid; idx < CLm*CLm; idx += 128) {
        int o = idx >> 5, i = idx & 31;
        w2T[i*CLm + o] = g2w[(size_t)h*CLm*CLm + idx];
    }
    if (tid < CLm) { b1s[tid] = g1b[h*CLm + tid]; b2s[tid] = g2b[h*CLm + tid]; }
    __syncthreads();

    for (int w = tid; w < WW; w += 128) {
        float h1[CLm];
#pragma unroll
        for (int o = 0; o < CLm; o++) h1[o] = b1s[o];
#pragma unroll 4
        for (int i = 0; i < CI; i++) {
            float xi = x_in[(size_t)i*NPIX + h*WW + w];
#pragma unroll
            for (int o = 0; o < CLm; o++) h1[o] = fmaf(xi, w1T[i*CLm + o], h1[o]);
        }
#pragma unroll
        for (int o = 0; o < CLm; o++) h1[o] = leakyf(h1[o]);
        float h2[CLm];
#pragma unroll
        for (int o = 0; o < CLm; o++) h2[o] = b2s[o];
#pragma unroll 4
        for (int i = 0; i < CLm; i++) {
            float v = h1[i];
#pragma unroll
            for (int o = 0; o < CLm; o++) h2[o] = fmaf(v, w2T[i*CLm + o], h2[o]);
        }
#pragma unroll
        for (int o = 0; o < CLm; o++)
            g_hf[(size_t)(h*CLm + o)*WW + w] = leakyf(h2[o]);
    }
}

// ---------------- K3: d3 GEMM split-K, FFMA2 inner (BM64,BN64,BK16,64 thr) -----
__global__ void __launch_bounds__(64)
k_gemm(const float* __restrict__ A)
{
    __shared__ float As[16][68];
    __shared__ float Bs[16][68];
    int t = threadIdx.x;           // 0..63
    int tx = t & 7, ty = t >> 3;   // tx -> n (pairs), ty -> m
    int bm = blockIdx.x * 64, bn = blockIdx.y * 64;
    int kbase = blockIdx.z * KSPL;
    unsigned long long acc2[8][4];
#pragma unroll
    for (int i = 0; i < 8; i++)
#pragma unroll
        for (int j = 0; j < 4; j++) acc2[i][j] = 0ull;

    for (int k0 = kbase; k0 < kbase + KSPL; k0 += 16) {
#pragma unroll
        for (int r = 0; r < 4; r++) {
            int c = t + 64*r;
            int row = c >> 2, kc = (c & 3) * 4;
            float4 a4 = *(const float4*)(A + (size_t)(bm+row)*KD + k0 + kc);
            As[kc+0][row] = a4.x; As[kc+1][row] = a4.y;
            As[kc+2][row] = a4.z; As[kc+3][row] = a4.w;
        }
#pragma unroll
        for (int r = 0; r < 4; r++) {
            int c = t + 64*r;
            int kk = c >> 4, nn = (c & 15) * 4;
            *(float4*)&Bs[kk][nn] =
                *(const float4*)(g_hf + (size_t)(k0+kk)*WW + bn + nn);
        }
        __syncthreads();
#pragma unroll
        for (int k = 0; k < 16; k++) {
            float4 a0 = *(const float4*)&As[k][ty*8];
            float4 a1 = *(const float4*)&As[k][ty*8+4];
            float av[8] = {a0.x,a0.y,a0.z,a0.w,a1.x,a1.y,a1.z,a1.w};
            unsigned long long a2[8];
#pragma unroll
            for (int i = 0; i < 8; i++) a2[i] = pack2(av[i], av[i]);
            unsigned long long b2[4];
#pragma unroll
            for (int j = 0; j < 4; j++)
                b2[j] = *(const unsigned long long*)&Bs[k][tx*8 + 2*j];
#pragma unroll
            for (int i = 0; i < 8; i++)
#pragma unroll
                for (int j = 0; j < 4; j++)
                    acc2[i][j] = fma2(a2[i], b2[j], acc2[i][j]);
        }
        __syncthreads();
    }
    float* outp = g_x1p + (size_t)blockIdx.z * M1 * WW;
    union U { unsigned long long u; float2 f; };
#pragma unroll
    for (int i = 0; i < 8; i++) {
        int row = bm + ty*8 + i;
        U u0, u1, u2, u3;
        u0.u = acc2[i][0]; u1.u = acc2[i][1]; u2.u = acc2[i][2]; u3.u = acc2[i][3];
        *(float4*)(outp + (size_t)row*WW + bn + tx*8)     =
            make_float4(u0.f.x, u0.f.y, u1.f.x, u1.f.y);
        *(float4*)(outp + (size_t)row*WW + bn + tx*8 + 4) =
            make_float4(u2.f.x, u2.f.y, u3.f.x, u3.f.y);
    }
}

// ---------------- K4: sum partials + bias, argmax -> inds1, CE loss[0] ----------
__global__ void k_s1head(const int* __restrict__ inds_gt, const float* __restrict__ bias)
{
    int pix = blockIdx.x * 256 + threadIdx.x;
    int h = pix >> 9, w = pix & 511;
    float v[16];
    float mx = -1e30f; int mi = 0;
#pragma unroll
    for (int c = 0; c < 16; c++) {
        float s = bias[h*16 + c];
#pragma unroll
        for (int z = 0; z < SPLITK; z++)
            s += g_x1p[(size_t)z*M1*WW + (size_t)(h*16 + c)*WW + w];
        v[c] = s;
        if (s > mx) { mx = s; mi = c; }
    }
    g_inds1[pix] = mi;
    int g = min(max(inds_gt[pix], 0), 4095);
    int t = g >> 8;
    float se = 0.f;
#pragma unroll
    for (int c = 0; c < 16; c++) se += expf(v[c] - mx);
    float nll = mx + logf(se) - v[t];

#pragma unroll
    for (int o = 16; o; o >>= 1) nll += __shfl_xor_sync(0xffffffffu, nll, o);
    __shared__ float red[8];
    int wz = threadIdx.x >> 5;
    if ((threadIdx.x & 31) == 0) red[wz] = nll;
    __syncthreads();
    if (threadIdx.x == 0) {
        float s = 0.f;
#pragma unroll
        for (int k = 0; k < 8; k++) s += red[k];
        atomicAdd(&g_acc[0], (double)s);
    }
}

// ---------------- bucketing: stage-2 (16 bins/row) ----------------
__global__ void __launch_bounds__(256)
k_bucket2(const int* __restrict__ inds_gt)
{
    __shared__ int cnt[16], cur[16], mcnt[3];
    int h = blockIdx.x, tid = threadIdx.x;
    int row = h << 9;
    if (tid < 16) cnt[tid] = 0;
    if (tid < 3) mcnt[tid] = 0;
    __syncthreads();
#pragma unroll
    for (int r = 0; r < 2; r++) {
        int p = tid + 256*r;
        atomicAdd(&cnt[g_inds1[row + p] & 15], 1);
        int g = min(max(inds_gt[row + p], 0), 4095);
#pragma unroll
        for (int i = -1; i <= 1; i++) {
            int i1 = min(max((g >> 8) + i, 0), 15);
            atomicAdd(&cnt[i1], 1);
            int tr = (g >> 4) - i1*16 + 8;
            if (tr >= 0 && tr < 32) atomicAdd(&mcnt[i+1], 1);
        }
    }
    __syncthreads();
    if (tid == 0) {
        int acc = 0;
        for (int e = 0; e < 16; e++) {
            g_off2[h*17 + e] = acc; cur[e] = acc; acc += cnt[e];
        }
        g_off2[h*17 + 16] = acc;
    }
    __syncthreads();
#pragma unroll
    for (int r = 0; r < 2; r++) {
        int p = tid + 256*r;
        int e = g_inds1[row + p] & 15;
        int slot = atomicAdd(&cur[e], 1) & 2047;         // defensive mask
        g_ent2[h*2048 + slot] = (unsigned)(p | (3u << 9));
        int g = min(max(inds_gt[row + p], 0), 4095);
#pragma unroll
        for (int i = -1; i <= 1; i++) {
            int i1 = min(max((g >> 8) + i, 0), 15);
            int tr = (g >> 4) - i1*16 + 8;
            int mk = (tr >= 0 && tr < 32) ? 1 : 0;
            int tt = min(max(tr, 0), 31);
            int s2 = atomicAdd(&cur[i1], 1) & 2047;      // defensive mask
            g_ent2[h*2048 + s2] =
                (unsigned)(p | ((i+1) << 9) | (tt << 11) | (mk << 16));
        }
    }
    __syncthreads();
    if (tid < 3) atomicAdd(&g_acc[8 + tid], (double)mcnt[tid]);
}

// ---------------- bucketing: stage-3 (256 bins/row) ----------------
__global__ void __launch_bounds__(256)
k_bucket3(const int* __restrict__ inds_gt)
{
    __shared__ int cnt[256], cur[256], mcnt[3];
    int h = blockIdx.x, tid = threadIdx.x;
    int row = h << 9;
    cnt[tid] = 0;
    if (tid < 3) mcnt[tid] = 0;
    __syncthreads();
#pragma unroll
    for (int r = 0; r < 2; r++) {
        int p = tid + 256*r;
        int raw = g_inds12[row + p];
        atomicAdd(&cnt[min(max(raw, 0), 255)], 1);
        int g = min(max(inds_gt[row + p], 0), 4095);
#pragma unroll
        for (int i = -1; i <= 1; i++) {
            int i12 = min(max((g >> 4) + i, 0), 255);
            atomicAdd(&cnt[i12], 1);
            int tr = g - i12*16 + 8;
            if (tr >= 0 && tr < 32) atomicAdd(&mcnt[i+1], 1);
        }
    }
    __syncthreads();
    if (tid == 0) {
        int acc = 0;
        for (int e = 0; e < 256; e++) {
            g_off3[h*257 + e] = acc; cur[e] = acc; acc += cnt[e];
        }
        g_off3[h*257 + 256] = acc;
    }
    __syncthreads();
#pragma unroll
    for (int r = 0; r < 2; r++) {
        int p = tid + 256*r;
        int raw = g_inds12[row + p];
        int e = min(max(raw, 0), 255);
        int slot = atomicAdd(&cur[e], 1) & 2047;         // defensive mask
        g_ent3[h*2048 + slot] = (unsigned)(p | (3u << 9));
        int g = min(max(inds_gt[row + p], 0), 4095);
#pragma unroll
        for (int i = -1; i <= 1; i++) {
            int i12 = min(max((g >> 4) + i, 0), 255);
            int tr = g - i12*16 + 8;
            int mk = (tr >= 0 && tr < 32) ? 1 : 0;
            int tt = min(max(tr, 0), 31);
            int s3 = atomicAdd(&cur[i12], 1) & 2047;     // defensive mask
            g_ent3[h*2048 + s3] =
                (unsigned)(p | ((i+1) << 9) | (tt << 11) | (mk << 16));
        }
    }
    __syncthreads();
    if (tid < 3) atomicAdd(&g_acc[11 + tid], (double)mcnt[tid]);
}

// ======== grouped gather machinery (natural [in][out] weight layout) ==========

__device__ __forceinline__ void eval4(
    const float* __restrict__ w1s, const float* __restrict__ w2s,
    const float* __restrict__ w3s,
    const float* __restrict__ b1s, const float* __restrict__ b2s,
    const float* __restrict__ b3s,
    const int* pix, float* xbw, float* ybw, int lane, float y3[4])
{
    {
        int jj = lane & 3, q = lane >> 2;
        const float* xp = g_xt + (size_t)pix[jj]*64;
#pragma unroll
        for (int r = 0; r < 8; r++)
            xbw[jj*68 + q + 8*r] = xp[q + 8*r];
    }
    __syncwarp();
    float a0 = b1s[lane], a1 = a0, a2 = a0, a3 = a0;
#pragma unroll
    for (int i4 = 0; i4 < 16; i4++) {
        float4 x0 = *(const float4*)(xbw + 0*68 + i4*4);
        float4 x1 = *(const float4*)(xbw + 1*68 + i4*4);
        float4 x2 = *(const float4*)(xbw + 2*68 + i4*4);
        float4 x3 = *(const float4*)(xbw + 3*68 + i4*4);
        const float* wp = w1s + i4*128 + lane;
        float w0 = wp[0], w1 = wp[32], w2 = wp[64], w3 = wp[96];
        a0 = fmaf(x0.x,w0,a0); a0 = fmaf(x0.y,w1,a0); a0 = fmaf(x0.z,w2,a0); a0 = fmaf(x0.w,w3,a0);
        a1 = fmaf(x1.x,w0,a1); a1 = fmaf(x1.y,w1,a1); a1 = fmaf(x1.z,w2,a1); a1 = fmaf(x1.w,w3,a1);
        a2 = fmaf(x2.x,w0,a2); a2 = fmaf(x2.y,w1,a2); a2 = fmaf(x2.z,w2,a2); a2 = fmaf(x2.w,w3,a2);
        a3 = fmaf(x3.x,w0,a3); a3 = fmaf(x3.y,w1,a3); a3 = fmaf(x3.z,w2,a3); a3 = fmaf(x3.w,w3,a3);
    }
    a0 = leakyf(a0); a1 = leakyf(a1); a2 = leakyf(a2); a3 = leakyf(a3);
    ybw[0*36+lane] = a0; ybw[1*36+lane] = a1; ybw[2*36+lane] = a2; ybw[3*36+lane] = a3;
    __syncwarp();
    float c0 = b2s[lane], c1 = c0, c2 = c0, c3 = c0;
#pragma unroll
    for (int i4 = 0; i4 < 8; i4++) {
        float4 x0 = *(const float4*)(ybw + 0*36 + i4*4);
        float4 x1 = *(const float4*)(ybw + 1*36 + i4*4);
        float4 x2 = *(const float4*)(ybw + 2*36 + i4*4);
        float4 x3 = *(const float4*)(ybw + 3*36 + i4*4);
        const float* wp = w2s + i4*128 + lane;
        float w0 = wp[0], w1 = wp[32], w2 = wp[64], w3 = wp[96];
        c0 = fmaf(x0.x,w0,c0); c0 = fmaf(x0.y,w1,c0); c0 = fmaf(x0.z,w2,c0); c0 = fmaf(x0.w,w3,c0);
        c1 = fmaf(x1.x,w0,c1); c1 = fmaf(x1.y,w1,c1); c1 = fmaf(x1.z,w2,c1); c1 = fmaf(x1.w,w3,c1);
        c2 = fmaf(x2.x,w0,c2); c2 = fmaf(x2.y,w1,c2); c2 = fmaf(x2.z,w2,c2); c2 = fmaf(x2.w,w3,c2);
        c3 = fmaf(x3.x,w0,c3); c3 = fmaf(x3.y,w1,c3); c3 = fmaf(x3.z,w2,c3); c3 = fmaf(x3.w,w3,c3);
    }
    c0 = leakyf(c0); c1 = leakyf(c1); c2 = leakyf(c2); c3 = leakyf(c3);
    __syncwarp();
    ybw[0*36+lane] = c0; ybw[1*36+lane] = c1; ybw[2*36+lane] = c2; ybw[3*36+lane] = c3;
    __syncwarp();
    float d0 = b3s[lane], d1 = d0, d2 = d0, d3 = d0;
#pragma unroll
    for (int i4 = 0; i4 < 8; i4++) {
        float4 x0 = *(const float4*)(ybw + 0*36 + i4*4);
        float4 x1 = *(const float4*)(ybw + 1*36 + i4*4);
        float4 x2 = *(const float4*)(ybw + 2*36 + i4*4);
        float4 x3 = *(const float4*)(ybw + 3*36 + i4*4);
        const float* wp = w3s + i4*128 + lane;
        float w0 = wp[0], w1 = wp[32], w2 = wp[64], w3 = wp[96];
        d0 = fmaf(x0.x,w0,d0); d0 = fmaf(x0.y,w1,d0); d0 = fmaf(x0.z,w2,d0); d0 = fmaf(x0.w,w3,d0);
        d1 = fmaf(x1.x,w0,d1); d1 = fmaf(x1.y,w1,d1); d1 = fmaf(x1.z,w2,d1); d1 = fmaf(x1.w,w3,d1);
        d2 = fmaf(x2.x,w0,d2); d2 = fmaf(x2.y,w1,d2); d2 = fmaf(x2.z,w2,d2); d2 = fmaf(x2.w,w3,d2);
        d3 = fmaf(x3.x,w0,d3); d3 = fmaf(x3.y,w1,d3); d3 = fmaf(x3.z,w2,d3); d3 = fmaf(x3.w,w3,d3);
    }
    y3[0] = d0; y3[1] = d1; y3[2] = d2; y3[3] = d3;
    __syncwarp();
}

struct SmemW {
    float w1s[2048], w2s[1024], w3s[1024];
    float b1s[32], b2s[32], b3s[32];
};

// K5: stage-2 fused; grid (16, 112), 256 threads, worklist from g_ent2
__global__ void __launch_bounds__(256)
k_s2all(const float* __restrict__ w1g, const float* __restrict__ b1g,
        const float* __restrict__ w2g, const float* __restrict__ b2g,
        const float* __restrict__ w3g, const float* __restrict__ b3g)
{
    __shared__ SmemW sw;
    __shared__ float xb[8][272];
    __shared__ float yb[8][144];
    __shared__ float nacc[3];

    int e = blockIdx.x, h = blockIdx.y;
    int tid = threadIdx.x;
    int row = h << 9;
    int off = g_off2[h*17 + e];
    int n   = g_off2[h*17 + e + 1] - off;
    off = min(max(off, 0), 2048);              // defensive clamp
    n   = min(max(n, 0), 2048 - off);
    if (tid < 3) nacc[tid] = 0.f;
    if (n == 0) return;

    size_t eg = (size_t)(e + 16*h);
    {
        const float4* s1 = (const float4*)(w1g + eg*2048);
        ((float4*)sw.w1s)[tid]       = s1[tid];
        ((float4*)sw.w1s)[tid + 256] = s1[tid + 256];
        ((float4*)sw.w2s)[tid] = ((const float4*)(w2g + eg*1024))[tid];
        ((float4*)sw.w3s)[tid] = ((const float4*)(w3g + eg*1024))[tid];
        if (tid < 32) {
            sw.b1s[tid] = b1g[eg*32 + tid];
            sw.b2s[tid] = b2g[eg*32 + tid];
            sw.b3s[tid] = b3g[eg*32 + tid];
        }
    }
    __syncthreads();

    int w = tid >> 5, lane = tid & 31;
    const unsigned* ent_p = g_ent2 + h*2048 + off;
    for (int base = w*4; base < n; base += 32) {
        int m = min(4, n - base);
        unsigned ent[4]; int pix[4];
#pragma unroll
        for (int j = 0; j < 4; j++) {
            ent[j] = ent_p[base + min(j, m-1)];
            pix[j] = row + (int)(ent[j] & 511u);
        }
        float y3[4];
        eval4(sw.w1s, sw.w2s, sw.w3s, sw.b1s, sw.b2s, sw.b3s,
              pix, xb[w], yb[w], lane, y3);
#pragma unroll
        for (int j = 0; j < 4; j++) {
            if (j >= m) break;
            int br = (ent[j] >> 9) & 3;
            float y = y3[j];
            if (br == 3) {
                float bvv = y; int bi = lane;
#pragma unroll
                for (int off2 = 16; off2; off2 >>= 1) {
                    float ov = __shfl_xor_sync(0xffffffffu, bvv, off2);
                    int   oi = __shfl_xor_sync(0xffffffffu, bi, off2);
                    if (ov > bvv || (ov == bvv && oi < bi)) { bvv = ov; bi = oi; }
                }
                if (lane == 0) g_inds12[pix[j]] = e*16 + bi - 8;
            } else {
                int tt = (ent[j] >> 11) & 31;
                float mv = y;
#pragma unroll
                for (int off2 = 16; off2; off2 >>= 1)
                    mv = fmaxf(mv, __shfl_xor_sync(0xffffffffu, mv, off2));
                float s = expf(y - mv);
#pragma unroll
                for (int off2 = 16; off2; off2 >>= 1)
                    s += __shfl_xor_sync(0xffffffffu, s, off2);
                float vt = __shfl_sync(0xffffffffu, y, tt);
                if (lane == 0) atomicAdd(&nacc[br], mv + logf(s) - vt);
            }
        }
    }
    __syncthreads();
    if (tid < 3) atomicAdd(&g_acc[1 + tid], (double)nacc[tid]);
}

// K6: stage-3 fused; grid (256, 112), 128 threads, worklist from g_ent3
__global__ void __launch_bounds__(128)
k_s3all(const float* __restrict__ w1g, const float* __restrict__ b1g,
        const float* __restrict__ w2g, const float* __restrict__ b2g,
        const float* __restrict__ w3g, const float* __restrict__ b3g,
        float* __restrict__ outF)
{
    __shared__ SmemW sw;
    __shared__ float xb[4][272];
    __shared__ float yb[4][144];
    __shared__ float nacc[3];

    int e = blockIdx.x, h = blockIdx.y;
    int tid = threadIdx.x;
    int row = h << 9;
    int off = g_off3[h*257 + e];
    int n   = g_off3[h*257 + e + 1] - off;
    off = min(max(off, 0), 2048);              // defensive clamp
    n   = min(max(n, 0), 2048 - off);
    if (tid < 3) nacc[tid] = 0.f;
    if (n == 0) return;

    size_t eg = (size_t)(e + 256*h);
    {
        const float4* s1 = (const float4*)(w1g + eg*2048);
        const float4* s2 = (const float4*)(w2g + eg*1024);
        const float4* s3 = (const float4*)(w3g + eg*1024);
#pragma unroll
        for (int r = 0; r < 4; r++)
            ((float4*)sw.w1s)[tid + 128*r] = s1[tid + 128*r];
#pragma unroll
        for (int r = 0; r < 2; r++) {
            ((float4*)sw.w2s)[tid + 128*r] = s2[tid + 128*r];
            ((float4*)sw.w3s)[tid + 128*r] = s3[tid + 128*r];
        }
        if (tid < 32) {
            sw.b1s[tid] = b1g[eg*32 + tid];
            sw.b2s[tid] = b2g[eg*32 + tid];
            sw.b3s[tid] = b3g[eg*32 + tid];
        }
    }
    __syncthreads();

    int w = tid >> 5, lane = tid & 31;
    const unsigned* ent_p = g_ent3 + h*2048 + off;
    for (int base = w*4; base < n; base += 16) {
        int m = min(4, n - base);
        unsigned ent[4]; int pix[4];
#pragma unroll
        for (int j = 0; j < 4; j++) {
            ent[j] = ent_p[base + min(j, m-1)];
            pix[j] = row + (int)(ent[j] & 511u);
        }
        float y3[4];
        eval4(sw.w1s, sw.w2s, sw.w3s, sw.b1s, sw.b2s, sw.b3s,
              pix, xb[w], yb[w], lane, y3);
#pragma unroll
        for (int j = 0; j < 4; j++) {
            if (j >= m) break;
            int br = (ent[j] >> 9) & 3;
            float y = y3[j];
            if (br == 3) {
                float bvv = y; int bi = lane;
#pragma unroll
                for (int off2 = 16; off2; off2 >>= 1) {
                    float ov = __shfl_xor_sync(0xffffffffu, bvv, off2);
                    int   oi = __shfl_xor_sync(0xffffffffu, bi, off2);
                    if (ov > bvv || (ov == bvv && oi < bi)) { bvv = ov; bi = oi; }
                }
                if (lane == 0) {
                    int raw = g_inds12[pix[j]];
                    outF[pix[j]] = (float)min(max(raw*16 + bi - 8, 0), 4095);
                }
            } else {
                int tt = (ent[j] >> 11) & 31;
                float mv = y;
#pragma unroll
                for (int off2 = 16; off2; off2 >>= 1)
                    mv = fmaxf(mv, __shfl_xor_sync(0xffffffffu, mv, off2));
                float s = expf(y - mv);
#pragma unroll
                for (int off2 = 16; off2; off2 >>= 1)
                    s += __shfl_xor_sync(0xffffffffu, s, off2);
                float vt = __shfl_sync(0xffffffffu, y, tt);
                if (lane == 0) atomicAdd(&nacc[br], mv + logf(s) - vt);
            }
        }
    }
    __syncthreads();
    if (tid < 3) atomicAdd(&g_acc[4 + tid], (double)nacc[tid]);
}

// ---------------- K8: finalize losses ----------------
__global__ void k_final(float* __restrict__ outF, int base)
{
    if (threadIdx.x == 0) {
        double N = (double)NPIX;
        outF[base] = (float)(g_acc[0] / N);
#pragma unroll
        for (int b = 0; b < 6; b++)
            outF[base + 1 + b] = (float)((g_acc[1 + b] / N) * (g_acc[8 + b] / N));
    }
}

// ---------------- launcher ----------------
extern "C" void kernel_launch(void* const* d_in, const int* in_sizes, int n_in,
                              void* d_out, int out_size)
{
    const float* x_in  = (const float*)d_in[0];
    const float* g1_w  = (const float*)d_in[1];
    const float* g1_b  = (const float*)d_in[2];
    const float* g2_w  = (const float*)d_in[3];
    const float* g2_b  = (const float*)d_in[4];
    const float* d3_w  = (const float*)d_in[5];
    const float* d3_b  = (const float*)d_in[6];
    const float* s2_w1 = (const float*)d_in[7];
    const float* s2_b1 = (const float*)d_in[8];
    const float* s2_w2 = (const float*)d_in[9];
    const float* s2_b2 = (const float*)d_in[10];
    const float* s2_w3 = (const float*)d_in[11];
    const float* s2_b3 = (const float*)d_in[12];
    const float* s3_w1 = (const float*)d_in[13];
    const float* s3_b1 = (const float*)d_in[14];
    const float* s3_w2 = (const float*)d_in[15];
    const float* s3_b2 = (const float*)d_in[16];
    const float* s3_w3 = (const float*)d_in[17];
    const float* s3_b3 = (const float*)d_in[18];
    const int*   igt   = (const int*)d_in[19];
    float* outF = (float*)d_out;

    k_zero<<<1, 32>>>();
    k_transpose<<<dim3(NPIX/32, CI/32), dim3(32, 8)>>>(x_in);
    k_stage1<<<HH, 128>>>(x_in, g1_w, g1_b, g2_w, g2_b);
    k_gemm<<<dim3(M1/64, WW/64, SPLITK), 64>>>(d3_w);
    k_s1head<<<NPIX/256, 256>>>(igt, d3_b);
    k_bucket2<<<HH, 256>>>(igt);
    k_s2all<<<dim3(16, HH), 256>>>(s2_w1, s2_b1, s2_w2, s2_b2, s2_w3, s2_b3);
    k_bucket3<<<HH, 256>>>(igt);
    k_s3all<<<dim3(256, HH), 128>>>(s3_w1, s3_b1, s3_w2, s3_b2, s3_w3, s3_b3, outF);
    k_final<<<1, 32>>>(outF, out_size - 7);
}

// round 11
// speedup vs baseline: 1.3298x; 1.0539x over previous
#include <cuda_runtime.h>
#include <math.h>

#define HH   112
#define WW   512
#define CI   64
#define CLm  32
#define NPIX (HH*WW)      // 57344
#define M1   (HH*16)      // 1792
#define KD   (HH*CLm)     // 3584
#define SPLITK 4
#define KSPL (KD/SPLITK)  // 896

// ---------------- scratch (static device globals; no allocation) ----------------
__device__ float  g_hf[KD*WW];           // [3584,512]  stage-1 output
__device__ float  g_x1p[SPLITK*M1*WW];   // split-K partials of d3 GEMM
__device__ float  g_xt[NPIX*CI];         // [pix,64]    transposed input
__device__ int    g_inds12[NPIX];        // UNCLIPPED inds12
__device__ double g_acc[16];             // [0]=ce1, [1..6]=branch nll, [8..13]=branch mask
__device__ unsigned g_ent2[HH*2048];     // stage-2 worklists per row
__device__ int      g_off2[HH*17];
__device__ unsigned g_ent3[HH*2048];     // stage-3 worklists per row
__device__ int      g_off3[HH*257];

__device__ __forceinline__ float leakyf(float v){ return v > 0.f ? v : 0.01f*v; }

__device__ __forceinline__ unsigned long long pack2(float lo, float hi){
    unsigned long long r;
    asm("mov.b64 %0, {%1, %2};" : "=l"(r) : "f"(lo), "f"(hi));
    return r;
}
__device__ __forceinline__ unsigned long long fma2(
    unsigned long long a, unsigned long long b, unsigned long long c){
    unsigned long long d;
    asm("fma.rn.f32x2 %0, %1, %2, %3;" : "=l"(d) : "l"(a), "l"(b), "l"(c));
    return d;
}

// ---------------- K0: zero accumulators ----------------
__global__ void k_zero()
{
    if (threadIdx.x < 16) g_acc[threadIdx.x] = 0.0;
}

// ---------------- K1: transpose x_in [ci,H,W] -> g_xt [pix,ci] ----------------
__global__ void k_transpose(const float* __restrict__ x_in)
{
    __shared__ float tile[32][33];
    int p0 = blockIdx.x * 32;
    int i0 = blockIdx.y * 32;
    int tx = threadIdx.x, ty = threadIdx.y;
#pragma unroll
    for (int r = ty; r < 32; r += 8)
        tile[r][tx] = x_in[(size_t)(i0 + r) * NPIX + p0 + tx];
    __syncthreads();
#pragma unroll
    for (int r = ty; r < 32; r += 8)
        g_xt[(size_t)(p0 + r) * CI + i0 + tx] = tile[tx][r];
}

// ---------------- K2: stage-1 grouped convs -> g_hf (256 threads) --------------
__global__ void __launch_bounds__(256)
k_stage1(const float* __restrict__ x_in,
         const float* __restrict__ g1w, const float* __restrict__ g1b,
         const float* __restrict__ g2w, const float* __restrict__ g2b)
{
    __shared__ float w1T[CI*CLm];   // [i][o]
    __shared__ float w2T[CLm*CLm];  // [i][o]
    __shared__ float b1s[CLm], b2s[CLm];
    int h = blockIdx.x, tid = threadIdx.x;
    for (int idx = tid; idx < CI*CLm; idx += 256) {
        int o = idx >> 6, i = idx & 63;
        w1T[i*CLm + o] = g1w[(size_t)h*CI*CLm + idx];
    }
    for (int idx = tid; idx < CLm*CLm; idx += 256) {
        int o = idx >> 5, i = idx & 31;
        w2T[i*CLm + o] = g2w[(size_t)h*CLm*CLm + idx];
    }
    if (tid < CLm) { b1s[tid] = g1b[h*CLm + tid]; b2s[tid] = g2b[h*CLm + tid]; }
    __syncthreads();

    for (int w = tid; w < WW; w += 256) {
        float h1[CLm];
#pragma unroll
        for (int o = 0; o < CLm; o++) h1[o] = b1s[o];
#pragma unroll 4
        for (int i = 0; i < CI; i++) {
            float xi = x_in[(size_t)i*NPIX + h*WW + w];
#pragma unroll
            for (int o = 0; o < CLm; o++) h1[o] = fmaf(xi, w1T[i*CLm + o], h1[o]);
        }
#pragma unroll
        for (int o = 0; o < CLm; o++) h1[o] = leakyf(h1[o]);
        float h2[CLm];
#pragma unroll
        for (int o = 0; o < CLm; o++) h2[o] = b2s[o];
#pragma unroll 4
        for (int i = 0; i < CLm; i++) {
            float v = h1[i];
#pragma unroll
            for (int o = 0; o < CLm; o++) h2[o] = fmaf(v, w2T[i*CLm + o], h2[o]);
        }
#pragma unroll
        for (int o = 0; o < CLm; o++)
            g_hf[(size_t)(h*CLm + o)*WW + w] = leakyf(h2[o]);
    }
}

// ---------------- K3: d3 GEMM split-K, FFMA2, software-pipelined ---------------
__global__ void __launch_bounds__(64)
k_gemm(const float* __restrict__ A)
{
    __shared__ float As[16][68];
    __shared__ float Bs[16][68];
    int t = threadIdx.x;           // 0..63
    int tx = t & 7, ty = t >> 3;   // tx -> n (pairs), ty -> m
    int bm = blockIdx.x * 64, bn = blockIdx.y * 64;
    int kbase = blockIdx.z * KSPL;
    int kend  = kbase + KSPL;
    unsigned long long acc2[8][4];
#pragma unroll
    for (int i = 0; i < 8; i++)
#pragma unroll
        for (int j = 0; j < 4; j++) acc2[i][j] = 0ull;

    int arow = (t) >> 2;                 // per-r arithmetic below
    float4 aPre[4], bPre[4];
    // prologue: fetch first tile
#pragma unroll
    for (int r = 0; r < 4; r++) {
        int c = t + 64*r;
        int row = c >> 2, kc = (c & 3) * 4;
        aPre[r] = *(const float4*)(A + (size_t)(bm+row)*KD + kbase + kc);
        int kk = c >> 4, nn = (c & 15) * 4;
        bPre[r] = *(const float4*)(g_hf + (size_t)(kbase+kk)*WW + bn + nn);
    }

    for (int k0 = kbase; k0 < kend; k0 += 16) {
        // stage prefetched tile into smem
#pragma unroll
        for (int r = 0; r < 4; r++) {
            int c = t + 64*r;
            int row = c >> 2, kc = (c & 3) * 4;
            As[kc+0][row] = aPre[r].x; As[kc+1][row] = aPre[r].y;
            As[kc+2][row] = aPre[r].z; As[kc+3][row] = aPre[r].w;
            int kk = c >> 4, nn = (c & 15) * 4;
            *(float4*)&Bs[kk][nn] = bPre[r];
        }
        __syncthreads();
        // prefetch next tile while computing this one
        if (k0 + 16 < kend) {
#pragma unroll
            for (int r = 0; r < 4; r++) {
                int c = t + 64*r;
                int row = c >> 2, kc = (c & 3) * 4;
                aPre[r] = *(const float4*)(A + (size_t)(bm+row)*KD + k0 + 16 + kc);
                int kk = c >> 4, nn = (c & 15) * 4;
                bPre[r] = *(const float4*)(g_hf + (size_t)(k0+16+kk)*WW + bn + nn);
            }
        }
#pragma unroll
        for (int k = 0; k < 16; k++) {
            float4 a0 = *(const float4*)&As[k][ty*8];
            float4 a1 = *(const float4*)&As[k][ty*8+4];
            float av[8] = {a0.x,a0.y,a0.z,a0.w,a1.x,a1.y,a1.z,a1.w};
            unsigned long long a2[8];
#pragma unroll
            for (int i = 0; i < 8; i++) a2[i] = pack2(av[i], av[i]);
            unsigned long long b2[4];
#pragma unroll
            for (int j = 0; j < 4; j++)
                b2[j] = *(const unsigned long long*)&Bs[k][tx*8 + 2*j];
#pragma unroll
            for (int i = 0; i < 8; i++)
#pragma unroll
                for (int j = 0; j < 4; j++)
                    acc2[i][j] = fma2(a2[i], b2[j], acc2[i][j]);
        }
        __syncthreads();
    }
    (void)arow;
    float* outp = g_x1p + (size_t)blockIdx.z * M1 * WW;
    union U { unsigned long long u; float2 f; };
#pragma unroll
    for (int i = 0; i < 8; i++) {
        int row = bm + ty*8 + i;
        U u0, u1, u2, u3;
        u0.u = acc2[i][0]; u1.u = acc2[i][1]; u2.u = acc2[i][2]; u3.u = acc2[i][3];
        *(float4*)(outp + (size_t)row*WW + bn + tx*8)     =
            make_float4(u0.f.x, u0.f.y, u1.f.x, u1.f.y);
        *(float4*)(outp + (size_t)row*WW + bn + tx*8 + 4) =
            make_float4(u2.f.x, u2.f.y, u3.f.x, u3.f.y);
    }
}

// ---------------- K4: fused s1 head + stage-2 bucketing (one block per row) ----
__global__ void __launch_bounds__(512)
k_s1bucket2(const int* __restrict__ inds_gt, const float* __restrict__ bias)
{
    __shared__ int cnt[16], cur[16], mcnt[3];
    __shared__ float red[16];
    int h = blockIdx.x, tid = threadIdx.x;
    int row = h << 9;
    int pix = row + tid;
    if (tid < 16) cnt[tid] = 0;
    if (tid < 3) mcnt[tid] = 0;
    __syncthreads();

    // argmax + CE over the 16 stage-1 channels (sum split-K partials + bias)
    float v[16];
    float mx = -1e30f; int mi = 0;
#pragma unroll
    for (int c = 0; c < 16; c++) {
        float s = bias[h*16 + c];
#pragma unroll
        for (int z = 0; z < SPLITK; z++)
            s += g_x1p[(size_t)z*M1*WW + (size_t)(h*16 + c)*WW + tid];
        v[c] = s;
        if (s > mx) { mx = s; mi = c; }
    }
    int g = min(max(inds_gt[pix], 0), 4095);
    int tcls = g >> 8;
    float se = 0.f;
#pragma unroll
    for (int c = 0; c < 16; c++) se += expf(v[c] - mx);
    float nll = mx + logf(se) - v[tcls];
#pragma unroll
    for (int o = 16; o; o >>= 1) nll += __shfl_xor_sync(0xffffffffu, nll, o);
    if ((tid & 31) == 0) red[tid >> 5] = nll;

    // bucket counts
    atomicAdd(&cnt[mi], 1);
#pragma unroll
    for (int i = -1; i <= 1; i++) {
        int i1 = min(max((g >> 8) + i, 0), 15);
        atomicAdd(&cnt[i1], 1);
        int tr = (g >> 4) - i1*16 + 8;
        if (tr >= 0 && tr < 32) atomicAdd(&mcnt[i+1], 1);
    }
    __syncthreads();
    if (tid == 0) {
        int acc = 0;
        for (int e = 0; e < 16; e++) {
            g_off2[h*17 + e] = acc; cur[e] = acc; acc += cnt[e];
        }
        g_off2[h*17 + 16] = acc;
        float sn = 0.f;
#pragma unroll
        for (int k = 0; k < 16; k++) sn += red[k];
        atomicAdd(&g_acc[0], (double)sn);
    }
    __syncthreads();
    // fill
    {
        int slot = atomicAdd(&cur[mi], 1) & 2047;
        g_ent2[h*2048 + slot] = (unsigned)(tid | (3u << 9));
    }
#pragma unroll
    for (int i = -1; i <= 1; i++) {
        int i1 = min(max((g >> 8) + i, 0), 15);
        int tr = (g >> 4) - i1*16 + 8;
        int mk = (tr >= 0 && tr < 32) ? 1 : 0;
        int tt = min(max(tr, 0), 31);
        int s2 = atomicAdd(&cur[i1], 1) & 2047;
        g_ent2[h*2048 + s2] =
            (unsigned)(tid | ((i+1) << 9) | (tt << 11) | (mk << 16));
    }
    __syncthreads();
    if (tid < 3) atomicAdd(&g_acc[8 + tid], (double)mcnt[tid]);
}

// ---------------- bucketing: stage-3 (256 bins/row) ----------------
__global__ void __launch_bounds__(256)
k_bucket3(const int* __restrict__ inds_gt)
{
    __shared__ int cnt[256], cur[256], mcnt[3];
    int h = blockIdx.x, tid = threadIdx.x;
    int row = h << 9;
    cnt[tid] = 0;
    if (tid < 3) mcnt[tid] = 0;
    __syncthreads();
#pragma unroll
    for (int r = 0; r < 2; r++) {
        int p = tid + 256*r;
        int raw = g_inds12[row + p];
        atomicAdd(&cnt[min(max(raw, 0), 255)], 1);
        int g = min(max(inds_gt[row + p], 0), 4095);
#pragma unroll
        for (int i = -1; i <= 1; i++) {
            int i12 = min(max((g >> 4) + i, 0), 255);
            atomicAdd(&cnt[i12], 1);
            int tr = g - i12*16 + 8;
            if (tr >= 0 && tr < 32) atomicAdd(&mcnt[i+1], 1);
        }
    }
    __syncthreads();
    if (tid == 0) {
        int acc = 0;
        for (int e = 0; e < 256; e++) {
            g_off3[h*257 + e] = acc; cur[e] = acc; acc += cnt[e];
        }
        g_off3[h*257 + 256] = acc;
    }
    __syncthreads();
#pragma unroll
    for (int r = 0; r < 2; r++) {
        int p = tid + 256*r;
        int raw = g_inds12[row + p];
        int e = min(max(raw, 0), 255);
        int slot = atomicAdd(&cur[e], 1) & 2047;
        g_ent3[h*2048 + slot] = (unsigned)(p | (3u << 9));
        int g = min(max(inds_gt[row + p], 0), 4095);
#pragma unroll
        for (int i = -1; i <= 1; i++) {
            int i12 = min(max((g >> 4) + i, 0), 255);
            int tr = g - i12*16 + 8;
            int mk = (tr >= 0 && tr < 32) ? 1 : 0;
            int tt = min(max(tr, 0), 31);
            int s3 = atomicAdd(&cur[i12], 1) & 2047;
            g_ent3[h*2048 + s3] =
                (unsigned)(p | ((i+1) << 9) | (tt << 11) | (mk << 16));
        }
    }
    __syncthreads();
    if (tid < 3) atomicAdd(&g_acc[11 + tid], (double)mcnt[tid]);
}

// ======== grouped gather machinery (natural [in][out] weight layout) ==========
// NOTE: xbw and ybw may ALIAS (ybw == xbw) — layer-1 input staging is dead
// before the first ybw store; __syncwarp() guards the cross-lane reuse.

__device__ __forceinline__ void eval4(
    const float* __restrict__ w1s, const float* __restrict__ w2s,
    const float* __restrict__ w3s,
    const float* __restrict__ b1s, const float* __restrict__ b2s,
    const float* __restrict__ b3s,
    const int* pix, float* xbw, float* ybw, int lane, float y3[4])
{
    {
        int jj = lane & 3, q = lane >> 2;
        const float* xp = g_xt + (size_t)pix[jj]*64;
#pragma unroll
        for (int r = 0; r < 8; r++)
            xbw[jj*68 + q + 8*r] = xp[q + 8*r];
    }
    __syncwarp();
    float a0 = b1s[lane], a1 = a0, a2 = a0, a3 = a0;
#pragma unroll
    for (int i4 = 0; i4 < 16; i4++) {
        float4 x0 = *(const float4*)(xbw + 0*68 + i4*4);
        float4 x1 = *(const float4*)(xbw + 1*68 + i4*4);
        float4 x2 = *(const float4*)(xbw + 2*68 + i4*4);
        float4 x3 = *(const float4*)(xbw + 3*68 + i4*4);
        const float* wp = w1s + i4*128 + lane;
        float w0 = wp[0], w1 = wp[32], w2 = wp[64], w3 = wp[96];
        a0 = fmaf(x0.x,w0,a0); a0 = fmaf(x0.y,w1,a0); a0 = fmaf(x0.z,w2,a0); a0 = fmaf(x0.w,w3,a0);
        a1 = fmaf(x1.x,w0,a1); a1 = fmaf(x1.y,w1,a1); a1 = fmaf(x1.z,w2,a1); a1 = fmaf(x1.w,w3,a1);
        a2 = fmaf(x2.x,w0,a2); a2 = fmaf(x2.y,w1,a2); a2 = fmaf(x2.z,w2,a2); a2 = fmaf(x2.w,w3,a2);
        a3 = fmaf(x3.x,w0,a3); a3 = fmaf(x3.y,w1,a3); a3 = fmaf(x3.z,w2,a3); a3 = fmaf(x3.w,w3,a3);
    }
    a0 = leakyf(a0); a1 = leakyf(a1); a2 = leakyf(a2); a3 = leakyf(a3);
    __syncwarp();           // xbw fully consumed before ybw (possibly aliased) is written
    ybw[0*36+lane] = a0; ybw[1*36+lane] = a1; ybw[2*36+lane] = a2; ybw[3*36+lane] = a3;
    __syncwarp();
    float c0 = b2s[lane], c1 = c0, c2 = c0, c3 = c0;
#pragma unroll
    for (int i4 = 0; i4 < 8; i4++) {
        float4 x0 = *(const float4*)(ybw + 0*36 + i4*4);
        float4 x1 = *(const float4*)(ybw + 1*36 + i4*4);
        float4 x2 = *(const float4*)(ybw + 2*36 + i4*4);
        float4 x3 = *(const float4*)(ybw + 3*36 + i4*4);
        const float* wp = w2s + i4*128 + lane;
        float w0 = wp[0], w1 = wp[32], w2 = wp[64], w3 = wp[96];
        c0 = fmaf(x0.x,w0,c0); c0 = fmaf(x0.y,w1,c0); c0 = fmaf(x0.z,w2,c0); c0 = fmaf(x0.w,w3,c0);
        c1 = fmaf(x1.x,w0,c1); c1 = fmaf(x1.y,w1,c1); c1 = fmaf(x1.z,w2,c1); c1 = fmaf(x1.w,w3,c1);
        c2 = fmaf(x2.x,w0,c2); c2 = fmaf(x2.y,w1,c2); c2 = fmaf(x2.z,w2,c2); c2 = fmaf(x2.w,w3,c2);
        c3 = fmaf(x3.x,w0,c3); c3 = fmaf(x3.y,w1,c3); c3 = fmaf(x3.z,w2,c3); c3 = fmaf(x3.w,w3,c3);
    }
    c0 = leakyf(c0); c1 = leakyf(c1); c2 = leakyf(c2); c3 = leakyf(c3);
    __syncwarp();
    ybw[0*36+lane] = c0; ybw[1*36+lane] = c1; ybw[2*36+lane] = c2; ybw[3*36+lane] = c3;
    __syncwarp();
    float d0 = b3s[lane], d1 = d0, d2 = d0, d3 = d0;
#pragma unroll
    for (int i4 = 0; i4 < 8; i4++) {
        float4 x0 = *(const float4*)(ybw + 0*36 + i4*4);
        float4 x1 = *(const float4*)(ybw + 1*36 + i4*4);
        float4 x2 = *(const float4*)(ybw + 2*36 + i4*4);
        float4 x3 = *(const float4*)(ybw + 3*36 + i4*4);
        const float* wp = w3s + i4*128 + lane;
        float w0 = wp[0], w1 = wp[32], w2 = wp[64], w3 = wp[96];
        d0 = fmaf(x0.x,w0,d0); d0 = fmaf(x0.y,w1,d0); d0 = fmaf(x0.z,w2,d0); d0 = fmaf(x0.w,w3,d0);
        d1 = fmaf(x1.x,w0,d1); d1 = fmaf(x1.y,w1,d1); d1 = fmaf(x1.z,w2,d1); d1 = fmaf(x1.w,w3,d1);
        d2 = fmaf(x2.x,w0,d2); d2 = fmaf(x2.y,w1,d2); d2 = fmaf(x2.z,w2,d2); d2 = fmaf(x2.w,w3,d2);
        d3 = fmaf(x3.x,w0,d3); d3 = fmaf(x3.y,w1,d3); d3 = fmaf(x3.z,w2,d3); d3 = fmaf(x3.w,w3,d3);
    }
    y3[0] = d0; y3[1] = d1; y3[2] = d2; y3[3] = d3;
    __syncwarp();
}

struct SmemW {
    float w1s[2048], w2s[1024], w3s[1024];
    float b1s[32], b2s[32], b3s[32];
};

// K5: stage-2 fused; grid (16, 112), 256 threads, worklist from g_ent2
__global__ void __launch_bounds__(256)
k_s2all(const float* __restrict__ w1g, const float* __restrict__ b1g,
        const float* __restrict__ w2g, const float* __restrict__ b2g,
        const float* __restrict__ w3g, const float* __restrict__ b3g)
{
    __shared__ SmemW sw;
    __shared__ float xb[8][272];        // also reused as ybw (aliased)
    __shared__ float nacc[3];

    int e = blockIdx.x, h = blockIdx.y;
    int tid = threadIdx.x;
    int row = h << 9;
    int off = g_off2[h*17 + e];
    int n   = g_off2[h*17 + e + 1] - off;
    off = min(max(off, 0), 2048);
    n   = min(max(n, 0), 2048 - off);
    if (tid < 3) nacc[tid] = 0.f;
    if (n == 0) return;

    size_t eg = (size_t)(e + 16*h);
    {
        const float4* s1 = (const float4*)(w1g + eg*2048);
        ((float4*)sw.w1s)[tid]       = s1[tid];
        ((float4*)sw.w1s)[tid + 256] = s1[tid + 256];
        ((float4*)sw.w2s)[tid] = ((const float4*)(w2g + eg*1024))[tid];
        ((float4*)sw.w3s)[tid] = ((const float4*)(w3g + eg*1024))[tid];
        if (tid < 32) {
            sw.b1s[tid] = b1g[eg*32 + tid];
            sw.b2s[tid] = b2g[eg*32 + tid];
            sw.b3s[tid] = b3g[eg*32 + tid];
        }
    }
    __syncthreads();

    int w = tid >> 5, lane = tid & 31;
    const unsigned* ent_p = g_ent2 + h*2048 + off;
    for (int base = w*4; base < n; base += 32) {
        int m = min(4, n - base);
        unsigned ent[4]; int pix[4];
#pragma unroll
        for (int j = 0; j < 4; j++) {
            ent[j] = ent_p[base + min(j, m-1)];
            pix[j] = row + (int)(ent[j] & 511u);
        }
        float y3[4];
        eval4(sw.w1s, sw.w2s, sw.w3s, sw.b1s, sw.b2s, sw.b3s,
              pix, xb[w], xb[w], lane, y3);
#pragma unroll
        for (int j = 0; j < 4; j++) {
            if (j >= m) break;
            int br = (ent[j] >> 9) & 3;
            float y = y3[j];
            if (br == 3) {
                float bvv = y; int bi = lane;
#pragma unroll
                for (int off2 = 16; off2; off2 >>= 1) {
                    float ov = __shfl_xor_sync(0xffffffffu, bvv, off2);
                    int   oi = __shfl_xor_sync(0xffffffffu, bi, off2);
                    if (ov > bvv || (ov == bvv && oi < bi)) { bvv = ov; bi = oi; }
                }
                if (lane == 0) g_inds12[pix[j]] = e*16 + bi - 8;
            } else {
                int tt = (ent[j] >> 11) & 31;
                float mv = y;
#pragma unroll
                for (int off2 = 16; off2; off2 >>= 1)
                    mv = fmaxf(mv, __shfl_xor_sync(0xffffffffu, mv, off2));
                float s = expf(y - mv);
#pragma unroll
                for (int off2 = 16; off2; off2 >>= 1)
                    s += __shfl_xor_sync(0xffffffffu, s, off2);
                float vt = __shfl_sync(0xffffffffu, y, tt);
                if (lane == 0) atomicAdd(&nacc[br], mv + logf(s) - vt);
            }
        }
    }
    __syncthreads();
    if (tid < 3) atomicAdd(&g_acc[1 + tid], (double)nacc[tid]);
}

// K6: stage-3 fused; grid (256, 112), 128 threads, worklist from g_ent3
__global__ void __launch_bounds__(128)
k_s3all(const float* __restrict__ w1g, const float* __restrict__ b1g,
        const float* __restrict__ w2g, const float* __restrict__ b2g,
        const float* __restrict__ w3g, const float* __restrict__ b3g,
        float* __restrict__ outF)
{
    __shared__ SmemW sw;
    __shared__ float xb[4][272];        // also reused as ybw (aliased)
    __shared__ float nacc[3];

    int e = blockIdx.x, h = blockIdx.y;
    int tid = threadIdx.x;
    int row = h << 9;
    int off = g_off3[h*257 + e];
    int n   = g_off3[h*257 + e + 1] - off;
    off = min(max(off, 0), 2048);
    n   = min(max(n, 0), 2048 - off);
    if (tid < 3) nacc[tid] = 0.f;
    if (n == 0) return;

    size_t eg = (size_t)(e + 256*h);
    {
        const float4* s1 = (const float4*)(w1g + eg*2048);
        const float4* s2 = (const float4*)(w2g + eg*1024);
        const float4* s3 = (const float4*)(w3g + eg*1024);
#pragma unroll
        for (int r = 0; r < 4; r++)
            ((float4*)sw.w1s)[tid + 128*r] = s1[tid + 128*r];
#pragma unroll
        for (int r = 0; r < 2; r++) {
            ((float4*)sw.w2s)[tid + 128*r] = s2[tid + 128*r];
            ((float4*)sw.w3s)[tid + 128*r] = s3[tid + 128*r];
        }
        if (tid < 32) {
            sw.b1s[tid] = b1g[eg*32 + tid];
            sw.b2s[tid] = b2g[eg*32 + tid];
            sw.b3s[tid] = b3g[eg*32 + tid];
        }
    }
    __syncthreads();

    int w = tid >> 5, lane = tid & 31;
    const unsigned* ent_p = g_ent3 + h*2048 + off;
    for (int base = w*4; base < n; base += 16) {
        int m = min(4, n - base);
        unsigned ent[4]; int pix[4];
#pragma unroll
        for (int j = 0; j < 4; j++) {
            ent[j] = ent_p[base + min(j, m-1)];
            pix[j] = row + (int)(ent[j] & 511u);
        }
        float y3[4];
        eval4(sw.w1s, sw.w2s, sw.w3s, sw.b1s, sw.b2s, sw.b3s,
              pix, xb[w], xb[w], lane, y3);
#pragma unroll
        for (int j = 0; j < 4; j++) {
            if (j >= m) break;
            int br = (ent[j] >> 9) & 3;
            float y = y3[j];
            if (br == 3) {
                float bvv = y; int bi = lane;
#pragma unroll
                for (int off2 = 16; off2; off2 >>= 1) {
                    float ov = __shfl_xor_sync(0xffffffffu, bvv, off2);
                    int   oi = __shfl_xor_sync(0xffffffffu, bi, off2);
                    if (ov > bvv || (ov == bvv && oi < bi)) { bvv = ov; bi = oi; }
                }
                if (lane == 0) {
                    int raw = g_inds12[pix[j]];
                    outF[pix[j]] = (float)min(max(raw*16 + bi - 8, 0), 4095);
                }
            } else {
                int tt = (ent[j] >> 11) & 31;
                float mv = y;
#pragma unroll
                for (int off2 = 16; off2; off2 >>= 1)
                    mv = fmaxf(mv, __shfl_xor_sync(0xffffffffu, mv, off2));
                float s = expf(y - mv);
#pragma unroll
                for (int off2 = 16; off2; off2 >>= 1)
                    s += __shfl_xor_sync(0xffffffffu, s, off2);
                float vt = __shfl_sync(0xffffffffu, y, tt);
                if (lane == 0) atomicAdd(&nacc[br], mv + logf(s) - vt);
            }
        }
    }
    __syncthreads();
    if (tid < 3) atomicAdd(&g_acc[4 + tid], (double)nacc[tid]);
}

// ---------------- K8: finalize losses ----------------
__global__ void k_final(float* __restrict__ outF, int base)
{
    if (threadIdx.x == 0) {
        double N = (double)NPIX;
        outF[base] = (float)(g_acc[0] / N);
#pragma unroll
        for (int b = 0; b < 6; b++)
            outF[base + 1 + b] = (float)((g_acc[1 + b] / N) * (g_acc[8 + b] / N));
    }
}

// ---------------- launcher ----------------
extern "C" void kernel_launch(void* const* d_in, const int* in_sizes, int n_in,
                              void* d_out, int out_size)
{
    const float* x_in  = (const float*)d_in[0];
    const float* g1_w  = (const float*)d_in[1];
    const float* g1_b  = (const float*)d_in[2];
    const float* g2_w  = (const float*)d_in[3];
    const float* g2_b  = (const float*)d_in[4];
    const float* d3_w  = (const float*)d_in[5];
    const float* d3_b  = (const float*)d_in[6];
    const float* s2_w1 = (const float*)d_in[7];
    const float* s2_b1 = (const float*)d_in[8];
    const float* s2_w2 = (const float*)d_in[9];
    const float* s2_b2 = (const float*)d_in[10];
    const float* s2_w3 = (const float*)d_in[11];
    const float* s2_b3 = (const float*)d_in[12];
    const float* s3_w1 = (const float*)d_in[13];
    const float* s3_b1 = (const float*)d_in[14];
    const float* s3_w2 = (const float*)d_in[15];
    const float* s3_b2 = (const float*)d_in[16];
    const float* s3_w3 = (const float*)d_in[17];
    const float* s3_b3 = (const float*)d_in[18];
    const int*   igt   = (const int*)d_in[19];
    float* outF = (float*)d_out;

    k_zero<<<1, 32>>>();
    k_transpose<<<dim3(NPIX/32, CI/32), dim3(32, 8)>>>(x_in);
    k_stage1<<<HH, 256>>>(x_in, g1_w, g1_b, g2_w, g2_b);
    k_gemm<<<dim3(M1/64, WW/64, SPLITK), 64>>>(d3_w);
    k_s1bucket2<<<HH, 512>>>(igt, d3_b);
    k_s2all<<<dim3(16, HH), 256>>>(s2_w1, s2_b1, s2_w2, s2_b2, s2_w3, s2_b3);
    k_bucket3<<<HH, 256>>>(igt);
    k_s3all<<<dim3(256, HH), 128>>>(s3_w1, s3_b1, s3_w2, s3_b2, s3_w3, s3_b3, outF);
    k_final<<<1, 32>>>(outF, out_size - 7);
}